// round 16
// baseline (speedup 1.0000x reference)
#include <cuda_runtime.h>
#include <cuda_bf16.h>
#include <cstdint>
#include <math.h>

#define B_   64
#define T_   1024
#define U_   300
#define G3_  900
#define M_   (B_*T_)
#define NBLK 120
#define RNN_THREADS 480

// ------------------ static device scratch ------------------
__device__ float g_xp[2][(size_t)M_ * G3_];   // xp per direction [m][900]
__device__ float g_h_t[2][2][U_][B_];         // [buf][dir][u][b]  (transposed)
__device__ unsigned char g_mask8[B_][T_];
__device__ __align__(128) int g_flag[8][15][32];  // [group][utile] step flags, 128B apart

typedef unsigned long long ull;

// ------------------ packed f32x2 primitives (mov-free) ------------------
__device__ __forceinline__ void fma2(ull& d, ull a, ull b) {
    asm("fma.rn.f32x2 %0, %1, %2, %0;" : "+l"(d) : "l"(a), "l"(b));
}
__device__ __forceinline__ ull bcast2(float x) {
    ull r; asm("mov.b64 %0, {%1, %1};" : "=l"(r) : "f"(x)); return r;
}
__device__ __forceinline__ void lds_v2u64(ull& a, ull& b, unsigned saddr) {
    asm volatile("ld.shared.v2.b64 {%0, %1}, [%2];" : "=l"(a), "=l"(b) : "r"(saddr));
}
__device__ __forceinline__ unsigned saddr_of(const void* p) {
    return (unsigned)__cvta_generic_to_shared(p);
}
__device__ __forceinline__ float lo2(ull v) { float2 f = *(float2*)&v; return f.x; }
__device__ __forceinline__ float hi2(ull v) { float2 f = *(float2*)&v; return f.y; }

__device__ __forceinline__ float sigmoidf_(float x) { return 1.0f / (1.0f + __expf(-x)); }
__device__ __forceinline__ float tanh_fast(float x) {
    float r; asm("tanh.approx.f32 %0, %1;" : "=f"(r) : "f"(x)); return r;
}

// ===========================================================
// init: detect mask dtype -> u8, zero h buf0, reset flags
// ===========================================================
__global__ void k_init(const void* __restrict__ mask_raw) {
    __shared__ int mode_s;
    int tid = threadIdx.x;
    if (tid == 0) {
        const unsigned char* b = (const unsigned char*)mask_raw;
        int mode;
        if (b[0] == 1) {
            if (b[1] != 0) mode = 0;                // bool (1 byte)
            else mode = (b[4] == 1) ? 1 : 2;        // int32 : int64
        } else {
            mode = (b[3] == 0x3f) ? 3 : 4;          // f32 : f64
        }
        mode_s = mode;
    }
    __syncthreads();
    int mode = mode_s;
    int stride = blockDim.x * gridDim.x;
    int g0 = blockIdx.x * blockDim.x + tid;
    for (int i = g0; i < 8 * 15 * 32; i += stride)
        ((int*)g_flag)[i] = 0;
    for (int i = g0; i < B_ * T_; i += stride) {
        unsigned char v;
        switch (mode) {
            case 0:  v = (((const unsigned char*)mask_raw)[i] != 0); break;
            case 1:  v = (((const int*)mask_raw)[i] != 0); break;
            case 2:  v = (((const long long*)mask_raw)[i] != 0); break;
            case 3:  v = (((const float*)mask_raw)[i] != 0.0f); break;
            default: v = (((const double*)mask_raw)[i] != 0.0); break;
        }
        ((unsigned char*)g_mask8)[i] = v;
    }
    for (int i = g0; i < 2 * U_ * B_; i += stride)
        ((float*)g_h_t)[i] = 0.0f;   // buf 0 (both dirs)
}

// nop shim: keeps ncu's skip-window aligned so k_rnn lands in the capture slot
__global__ void k_nop() {
    if (blockIdx.x == 0 && threadIdx.x == 0) g_flag[0][0][16] = 0;  // unused pad slot
}

// ===========================================================
// xp GEMM: xp[d][m][j] = sum_k x[m][k]*K_d[k][j] + b_in[j]
// 64x64 tile, k-tile 16, 4x4/thread via mov-free FFMA2
// grid (1024, 15, 2), 256 threads
// ===========================================================
__global__ void __launch_bounds__(256)
k_xp(const float* __restrict__ x,
     const float* __restrict__ kf, const float* __restrict__ kb,
     const float* __restrict__ bf, const float* __restrict__ bb) {
    const int bm = blockIdx.x, bn = blockIdx.y, d = blockIdx.z;
    const float* W    = d ? kb : kf;
    const float* bias = d ? bb : bf;     // row 0 = input bias
    float* C = g_xp[d];

    __shared__ float As[16 * 68];        // A[k][m], pitch 68
    __shared__ float Ws[16 * 68];        // W[k][n], pitch 68

    const int tid = threadIdx.x;
    const int tx = tid & 15, ty = tid >> 4;
    const int m0 = bm * 64, n0 = bn * 64;

    ull acc[4][2];
#pragma unroll
    for (int i = 0; i < 4; i++) { acc[i][0] = 0ull; acc[i][1] = 0ull; }

    const unsigned ws_base = saddr_of(Ws) + tx * 16;

    for (int kt = 0; kt < 304; kt += 16) {
        {   // A: 64 rows x 16 k -> transposed
            int r = tid >> 2, q = tid & 3;
            int k = kt + q * 4;
            float4 v = make_float4(0.f,0.f,0.f,0.f);
            if (k < 300) v = *(const float4*)(x + (size_t)(m0 + r) * 300 + k);
            As[(q*4+0)*68 + r] = v.x; As[(q*4+1)*68 + r] = v.y;
            As[(q*4+2)*68 + r] = v.z; As[(q*4+3)*68 + r] = v.w;
        }
        {   // W: 16 k x 64 n
            int kk = tid >> 4, c4 = tid & 15;
            int k = kt + kk, j = n0 + c4 * 4;
            float4 v = make_float4(0.f,0.f,0.f,0.f);
            if (k < 300 && j < 900) v = *(const float4*)(W + (size_t)k * 900 + j);
            *(float4*)&Ws[kk*68 + c4*4] = v;
        }
        __syncthreads();
#pragma unroll
        for (int kk = 0; kk < 16; kk++) {
            float4 a = *(const float4*)&As[kk*68 + ty*4];
            ull w01, w23;
            lds_v2u64(w01, w23, ws_base + kk * 272);
            ull a0 = bcast2(a.x), a1 = bcast2(a.y), a2 = bcast2(a.z), a3 = bcast2(a.w);
            fma2(acc[0][0], a0, w01); fma2(acc[0][1], a0, w23);
            fma2(acc[1][0], a1, w01); fma2(acc[1][1], a1, w23);
            fma2(acc[2][0], a2, w01); fma2(acc[2][1], a2, w23);
            fma2(acc[3][0], a3, w01); fma2(acc[3][1], a3, w23);
        }
        __syncthreads();
    }
    int j = n0 + tx * 4;
    if (j < 900) {
        float b0 = bias[j], b1 = bias[j+1], b2 = bias[j+2], b3 = bias[j+3];
#pragma unroll
        for (int i = 0; i < 4; i++) {
            int m = m0 + ty * 4 + i;
            float4 o;
            o.x = lo2(acc[i][0]) + b0; o.y = hi2(acc[i][0]) + b1;
            o.z = lo2(acc[i][1]) + b2; o.w = hi2(acc[i][1]) + b3;
            *(float4*)(C + (size_t)m * 900 + j) = o;
        }
    }
}

// ===========================================================
// persistent recurrent kernel: 120 blocks x 480 threads
// block = (dir, utile of 20 units, btile of 16 batches)
// GEMM: warp w = k-slice of 20 units (produced by block (d,w,btile));
//       lane = (batch 0-15, col-half {0..31}/{32..59}) -> 16-aligned bases.
//       All lanes run the uniform 16-ull inner loop; chalf=1 stores 14.
// Per-producer flags: warp waits ONLY on its k-slice's producer.
// h-carry kept in gate-thread registers (no ho reload).
// ===========================================================
#define SM_W   (300*60)
#define SM_RP  (15*16*60)
#define SM_BR  64
#define SM_PAD 16
#define SMEM_FLOATS (SM_W + SM_RP + SM_BR + SM_PAD)
#define SMEM_BYTES  (SMEM_FLOATS*4)

__global__ void __launch_bounds__(RNN_THREADS, 1)
k_rnn(const float* __restrict__ rkf, const float* __restrict__ rkb,
      const float* __restrict__ bf,  const float* __restrict__ bb,
      float* __restrict__ out) {
    extern __shared__ float sm[];
    float* w_s    = sm;                  // [300][60] (+pad tail for uniform overread)
    float* rp_s   = sm + SM_W;           // [15][16][60]
    float* brec_s = rp_s + SM_RP;        // [60]

    const int tid  = threadIdx.x;
    const int lane = tid & 31;
    const int bx   = blockIdx.x;
    const int d    = bx / 60;
    const int rr_  = bx % 60;
    const int ut   = rr_ >> 2;           // this block's unit-tile (produces these 20 u)
    const int u0   = ut * 20;
    const int btile = (rr_ & 3) * 16;
    const int gid  = d * 4 + (rr_ & 3);  // flag group (d, btile)
    int* myflag = &g_flag[gid][ut][0];
    const float* rk   = d ? rkb : rkf;
    const float* brec = (d ? bb : bf) + 900;   // row 1 = recurrent bias
    const float* xp   = g_xp[d];

    // resident recurrent weight slice: w_s[k][c], c = gate-major 3x20
    for (int i = tid; i < 300*60; i += RNN_THREADS) {
        int k = i / 60, c = i % 60;
        int g = (c < 20) ? (u0 + c) : (c < 40) ? (300 + u0 + c - 20) : (600 + u0 + c - 40);
        w_s[k*60 + c] = rk[(size_t)k*900 + g];
    }
    if (tid < 60) {
        int c = tid;
        int g = (c < 20) ? (u0 + c) : (c < 40) ? (300 + u0 + c - 20) : (600 + u0 + c - 40);
        brec_s[c] = brec[g];
    }
    __syncthreads();

    // GEMM task: warp = kg (k-slice of 20 u), lane -> (b, colhalf)
    const int kg = tid >> 5;             // 0..14
    const int gbm = lane & 15;           // batch within tile
    const int chalf = lane >> 4;         // 0: cols 0..31, 1: cols 32..59
    const int c0 = chalf << 5;           // {0, 32} -> 16B-aligned bases
    const int nstore = chalf ? 14 : 16;  // valid ull accumulators
    const unsigned w_base = saddr_of(w_s) + (kg * 20) * 240 + c0 * 4;
    int* prodflag = &g_flag[gid][kg][0];

    // gate task: tid<320 -> (b, u)
    const int gb = tid / 20, gu = tid % 20;
    const int bg = btile + gb;
    const float* xpg = xp + (size_t)bg * T_ * 900 + u0 + gu;

    // prefetch xp + mask for s = 0; h-carry starts at 0
    float xz = 0.f, xr = 0.f, xh = 0.f, hcarry = 0.f;
    unsigned char mpref = 0;
    if (tid < 320) {
        const int t0 = d ? (T_ - 1) : 0;
        const float* p = xpg + (size_t)t0 * 900;
        xz = __ldcg(p); xr = __ldcg(p + 300); xh = __ldcg(p + 600);
        mpref = g_mask8[bg][t0];
    }

    for (int s = 0; s < T_; s++) {
        const int t = d ? (T_ - 1 - s) : s;
        const int cur = s & 1, nxt = cur ^ 1;

        // per-warp wait: only this k-slice's producer must have finished step s-1
        if (s > 0) {
            if (lane == 0) {
                int v, spins = 0;
                for (;;) {
                    asm volatile("ld.acquire.gpu.global.s32 %0, [%1];"
                                 : "=r"(v) : "l"(prodflag) : "memory");
                    if (v >= s) break;
                    if (++spins > 64) __nanosleep(64);
                }
            }
            __syncwarp();
        }

        // front-batch this thread's 20 h values (contiguous 64B per u-row per warp)
        float hv[20];
        {
            const float* hp = &g_h_t[cur][d][kg * 20][btile + gbm];
#pragma unroll
            for (int k = 0; k < 20; k++) hv[k] = __ldcg(hp + k * B_);
        }

        // rp partial: 1 batch x 32 cols over 20 k (uniform; chalf=1 keeps 28)
        {
            ull a[16];
#pragma unroll
            for (int i = 0; i < 16; i++) a[i] = 0ull;
            unsigned wa = w_base;
#pragma unroll
            for (int k = 0; k < 20; k++) {
                ull hA = bcast2(hv[k]);
                ull w0,w1,w2,w3,w4,w5,w6,w7,w8,w9,wA,wB,wC,wD,wE,wF;
                lds_v2u64(w0, w1, wa);
                lds_v2u64(w2, w3, wa + 16);
                lds_v2u64(w4, w5, wa + 32);
                lds_v2u64(w6, w7, wa + 48);
                lds_v2u64(w8, w9, wa + 64);
                lds_v2u64(wA, wB, wa + 80);
                lds_v2u64(wC, wD, wa + 96);
                lds_v2u64(wE, wF, wa + 112);
                fma2(a[0],hA,w0);  fma2(a[1],hA,w1);  fma2(a[2],hA,w2);
                fma2(a[3],hA,w3);  fma2(a[4],hA,w4);  fma2(a[5],hA,w5);
                fma2(a[6],hA,w6);  fma2(a[7],hA,w7);  fma2(a[8],hA,w8);
                fma2(a[9],hA,w9);  fma2(a[10],hA,wA); fma2(a[11],hA,wB);
                fma2(a[12],hA,wC); fma2(a[13],hA,wD); fma2(a[14],hA,wE);
                fma2(a[15],hA,wF);
                wa += 240;
            }
            ull* rp = (ull*)(rp_s + ((kg*16 + gbm) * 60 + c0));
#pragma unroll
            for (int i = 0; i < 14; i++) rp[i] = a[i];
            if (nstore == 16) { rp[14] = a[14]; rp[15] = a[15]; }
        }
        __syncthreads();

        // gates: reduce 15 k-slice partials, update state, store h FIRST
        if (tid < 320) {
            float rz = brec_s[gu], rg = brec_s[20+gu], rh = brec_s[40+gu];
#pragma unroll
            for (int q = 0; q < 15; q++) {
                const float* rp = rp_s + (q*16 + gb) * 60;
                rz += rp[gu]; rg += rp[20+gu]; rh += rp[40+gu];
            }
            float ho = hcarry;
            float z  = sigmoidf_(xz + rz);
            float r  = sigmoidf_(xr + rg);
            float hh = tanh_fast(xh + r * rh);
            float hn = z * ho + (1.f - z) * hh;
            float hc = mpref ? hn : ho;
            float y  = mpref ? hn : 0.f;
            hcarry = hc;
            __stcg(&g_h_t[nxt][d][u0 + gu][bg], hc);
            xz = y;   // stash y; xz is reloaded in the tail prefetch
        }

        // publish: h stores drained block-wide, then single release store
        __syncthreads();
        if (tid == 0) {
            asm volatile("st.release.gpu.global.s32 [%0], %1;"
                         :: "l"(myflag), "r"(s + 1) : "memory");
        }

        // off-critical-path tail: y store + prefetch next xp/mask
        if (tid < 320) {
            out[((size_t)bg * T_ + t) * 600 + d * 300 + u0 + gu] = xz;
            if (s + 1 < T_) {
                const int tn = d ? (T_ - 2 - s) : (s + 1);
                const float* p = xpg + (size_t)tn * 900;
                xz = __ldcg(p); xr = __ldcg(p + 300); xh = __ldcg(p + 600);
                mpref = g_mask8[bg][tn];
            }
        }
    }
}

// ===========================================================
// state = relu(concat(h_f, h_b) @ w_fc + b_fc), grid (64 b, 5 u-tiles)
// ===========================================================
__global__ void __launch_bounds__(256)
k_fc(const float* __restrict__ wfc, const float* __restrict__ bfc,
     float* __restrict__ out) {
    __shared__ float hc[600];
    __shared__ float part[4][64];
    const int b = blockIdx.x, u0 = blockIdx.y * 60, tid = threadIdx.x;
    for (int i = tid; i < 300; i += 256) {
        hc[i]       = g_h_t[0][0][i][b];   // final h lives in buffer 0 (T=1024 even)
        hc[300 + i] = g_h_t[0][1][i][b];
    }
    __syncthreads();
    if (tid < 240) {
        int ut = tid % 60, kg = tid / 60;
        int u = u0 + ut;
        float acc = 0.f;
        const float* wp = wfc + (size_t)(kg*150) * 300 + u;
#pragma unroll 10
        for (int k = 0; k < 150; k++) acc = fmaf(hc[kg*150 + k], wp[(size_t)k*300], acc);
        part[kg][ut] = acc;
    }
    __syncthreads();
    if (tid < 60) {
        float v = part[0][tid] + part[1][tid] + part[2][tid] + part[3][tid] + bfc[u0 + tid];
        out[(size_t)B_ * T_ * 600 + (size_t)b * 300 + u0 + tid] = fmaxf(v, 0.f);
    }
}

// ===========================================================
extern "C" void kernel_launch(void* const* d_in, const int* in_sizes, int n_in,
                              void* d_out, int out_size) {
    const float* x    = (const float*)d_in[0];
    const void*  mask = d_in[1];
    const float* kf   = (const float*)d_in[2];
    const float* rkf  = (const float*)d_in[3];
    const float* bf   = (const float*)d_in[4];
    const float* kb   = (const float*)d_in[5];
    const float* rkb  = (const float*)d_in[6];
    const float* bb   = (const float*)d_in[7];
    const float* wfc  = (const float*)d_in[8];
    const float* bfc  = (const float*)d_in[9];
    float* out = (float*)d_out;

    cudaFuncSetAttribute(k_rnn, cudaFuncAttributeMaxDynamicSharedMemorySize, SMEM_BYTES);

    k_init<<<32, 256>>>(mask);
    k_xp<<<dim3(1024, 15, 2), 256>>>(x, kf, kb, bf, bb);
    k_nop<<<1, 32>>>();   // keeps ncu capture window on k_rnn
    k_rnn<<<NBLK, RNN_THREADS, SMEM_BYTES>>>(rkf, rkb, bf, bb, out);
    k_fc<<<dim3(B_, 5), 256>>>(wfc, bfc, out);
}

// round 17
// speedup vs baseline: 1.1015x; 1.1015x over previous
#include <cuda_runtime.h>
#include <cuda_bf16.h>
#include <cstdint>
#include <math.h>

#define B_   64
#define T_   1024
#define U_   300
#define G3_  900
#define M_   (B_*T_)
#define NBLK 120
#define RNN_THREADS 480

// ------------------ static device scratch ------------------
__device__ float g_xp[2][(size_t)M_ * G3_];   // xp per direction [m][900]
__device__ float g_h_t[2][2][U_][B_];         // [buf][dir][u][b]  (transposed)
__device__ unsigned char g_mask8[B_][T_];
__device__ __align__(128) int g_barc[8][32];  // one group counter per 128B line

typedef unsigned long long ull;

// ------------------ packed f32x2 primitives (mov-free) ------------------
__device__ __forceinline__ void fma2(ull& d, ull a, ull b) {
    asm("fma.rn.f32x2 %0, %1, %2, %0;" : "+l"(d) : "l"(a), "l"(b));
}
__device__ __forceinline__ ull bcast2(float x) {
    ull r; asm("mov.b64 %0, {%1, %1};" : "=l"(r) : "f"(x)); return r;
}
__device__ __forceinline__ void lds_v2u64(ull& a, ull& b, unsigned saddr) {
    asm volatile("ld.shared.v2.b64 {%0, %1}, [%2];" : "=l"(a), "=l"(b) : "r"(saddr));
}
__device__ __forceinline__ void lds_v2f32(float& a, float& b, unsigned saddr) {
    asm volatile("ld.shared.v2.f32 {%0, %1}, [%2];" : "=f"(a), "=f"(b) : "r"(saddr));
}
__device__ __forceinline__ unsigned saddr_of(const void* p) {
    return (unsigned)__cvta_generic_to_shared(p);
}
__device__ __forceinline__ float lo2(ull v) { float2 f = *(float2*)&v; return f.x; }
__device__ __forceinline__ float hi2(ull v) { float2 f = *(float2*)&v; return f.y; }

__device__ __forceinline__ float sigmoidf_(float x) { return 1.0f / (1.0f + __expf(-x)); }
__device__ __forceinline__ float tanh_fast(float x) {
    float r; asm("tanh.approx.f32 %0, %1;" : "=f"(r) : "f"(x)); return r;
}

// ===========================================================
// init: detect mask dtype -> u8, zero h buf0, reset barriers
// ===========================================================
__global__ void k_init(const void* __restrict__ mask_raw) {
    __shared__ int mode_s;
    int tid = threadIdx.x;
    if (tid == 0) {
        const unsigned char* b = (const unsigned char*)mask_raw;
        int mode;
        if (b[0] == 1) {
            if (b[1] != 0) mode = 0;                // bool (1 byte)
            else mode = (b[4] == 1) ? 1 : 2;        // int32 : int64
        } else {
            mode = (b[3] == 0x3f) ? 3 : 4;          // f32 : f64
        }
        mode_s = mode;
    }
    if (blockIdx.x == 0 && tid < 8 * 32) ((int*)g_barc)[tid] = 0;
    __syncthreads();
    int mode = mode_s;
    int stride = blockDim.x * gridDim.x;
    int g0 = blockIdx.x * blockDim.x + tid;
    for (int i = g0; i < B_ * T_; i += stride) {
        unsigned char v;
        switch (mode) {
            case 0:  v = (((const unsigned char*)mask_raw)[i] != 0); break;
            case 1:  v = (((const int*)mask_raw)[i] != 0); break;
            case 2:  v = (((const long long*)mask_raw)[i] != 0); break;
            case 3:  v = (((const float*)mask_raw)[i] != 0.0f); break;
            default: v = (((const double*)mask_raw)[i] != 0.0); break;
        }
        ((unsigned char*)g_mask8)[i] = v;
    }
    for (int i = g0; i < 2 * U_ * B_; i += stride)
        ((float*)g_h_t)[i] = 0.0f;   // buf 0 (both dirs)
}

// nop shim: keeps ncu's skip-window aligned so k_rnn lands in the capture slot
__global__ void k_nop() {
    if (blockIdx.x == 0 && threadIdx.x == 0) g_barc[0][16] = 0;  // unused pad slot
}

// ===========================================================
// xp GEMM: xp[d][m][j] = sum_k x[m][k]*K_d[k][j] + b_in[j]
// 64x64 tile, k-tile 16, 4x4/thread via mov-free FFMA2
// grid (1024, 15, 2), 256 threads
// ===========================================================
__global__ void __launch_bounds__(256)
k_xp(const float* __restrict__ x,
     const float* __restrict__ kf, const float* __restrict__ kb,
     const float* __restrict__ bf, const float* __restrict__ bb) {
    const int bm = blockIdx.x, bn = blockIdx.y, d = blockIdx.z;
    const float* W    = d ? kb : kf;
    const float* bias = d ? bb : bf;     // row 0 = input bias
    float* C = g_xp[d];

    __shared__ float As[16 * 68];        // A[k][m], pitch 68
    __shared__ float Ws[16 * 68];        // W[k][n], pitch 68

    const int tid = threadIdx.x;
    const int tx = tid & 15, ty = tid >> 4;
    const int m0 = bm * 64, n0 = bn * 64;

    ull acc[4][2];
#pragma unroll
    for (int i = 0; i < 4; i++) { acc[i][0] = 0ull; acc[i][1] = 0ull; }

    const unsigned ws_base = saddr_of(Ws) + tx * 16;

    for (int kt = 0; kt < 304; kt += 16) {
        {   // A: 64 rows x 16 k -> transposed
            int r = tid >> 2, q = tid & 3;
            int k = kt + q * 4;
            float4 v = make_float4(0.f,0.f,0.f,0.f);
            if (k < 300) v = *(const float4*)(x + (size_t)(m0 + r) * 300 + k);
            As[(q*4+0)*68 + r] = v.x; As[(q*4+1)*68 + r] = v.y;
            As[(q*4+2)*68 + r] = v.z; As[(q*4+3)*68 + r] = v.w;
        }
        {   // W: 16 k x 64 n
            int kk = tid >> 4, c4 = tid & 15;
            int k = kt + kk, j = n0 + c4 * 4;
            float4 v = make_float4(0.f,0.f,0.f,0.f);
            if (k < 300 && j < 900) v = *(const float4*)(W + (size_t)k * 900 + j);
            *(float4*)&Ws[kk*68 + c4*4] = v;
        }
        __syncthreads();
#pragma unroll
        for (int kk = 0; kk < 16; kk++) {
            float4 a = *(const float4*)&As[kk*68 + ty*4];
            ull w01, w23;
            lds_v2u64(w01, w23, ws_base + kk * 272);
            ull a0 = bcast2(a.x), a1 = bcast2(a.y), a2 = bcast2(a.z), a3 = bcast2(a.w);
            fma2(acc[0][0], a0, w01); fma2(acc[0][1], a0, w23);
            fma2(acc[1][0], a1, w01); fma2(acc[1][1], a1, w23);
            fma2(acc[2][0], a2, w01); fma2(acc[2][1], a2, w23);
            fma2(acc[3][0], a3, w01); fma2(acc[3][1], a3, w23);
        }
        __syncthreads();
    }
    int j = n0 + tx * 4;
    if (j < 900) {
        float b0 = bias[j], b1 = bias[j+1], b2 = bias[j+2], b3 = bias[j+3];
#pragma unroll
        for (int i = 0; i < 4; i++) {
            int m = m0 + ty * 4 + i;
            float4 o;
            o.x = lo2(acc[i][0]) + b0; o.y = hi2(acc[i][0]) + b1;
            o.z = lo2(acc[i][1]) + b2; o.w = hi2(acc[i][1]) + b3;
            *(float4*)(C + (size_t)m * 900 + j) = o;
        }
    }
}

// ===========================================================
// persistent recurrent kernel: 120 blocks x 480 threads
// block = (dir, utile 20 units -> 60 gate cols, btile 16 batches)
// GEMM: warp = k-slice (20 k); lane = col-pair (30 active);
//       each thread covers ALL 16 batches (8 f32x2 accumulators/col).
//       Weights read once per element; h broadcast from per-warp smem.
// Sync: R14-style group counter (15 blocks), per-warp acquire spin.
// ===========================================================
#define SM_W   (300*60)
#define SM_H   (300*20)
#define SM_RP  (15*60*16)
#define SM_BR  64
#define SMEM_FLOATS (SM_W + SM_H + SM_RP + SM_BR)
#define SMEM_BYTES  (SMEM_FLOATS*4)

__global__ void __launch_bounds__(RNN_THREADS, 1)
k_rnn(const float* __restrict__ rkf, const float* __restrict__ rkb,
      const float* __restrict__ bf,  const float* __restrict__ bb,
      float* __restrict__ out) {
    extern __shared__ float sm[];
    float* w_s    = sm;                  // [300][60]
    float* h_s    = sm + SM_W;           // [300][20] (16 used, pitch 80B for v2.b64 align)
    float* rp_s   = h_s + SM_H;          // [15 kg][60 col][16 b]
    float* brec_s = rp_s + SM_RP;        // [60]

    const int tid  = threadIdx.x;
    const int lane = tid & 31;
    const int bx   = blockIdx.x;
    const int d    = bx / 60;
    const int rr_  = bx % 60;
    const int u0   = (rr_ >> 2) * 20;
    const int btile = (rr_ & 3) * 16;
    const int gid  = d * 4 + (rr_ & 3);  // barrier group (d, btile)
    int* bar = &g_barc[gid][0];
    const float* rk   = d ? rkb : rkf;
    const float* brec = (d ? bb : bf) + 900;   // row 1 = recurrent bias
    const float* xp   = g_xp[d];

    // resident recurrent weight slice: w_s[k][c], c = gate-major 3x20
    for (int i = tid; i < 300*60; i += RNN_THREADS) {
        int k = i / 60, c = i % 60;
        int g = (c < 20) ? (u0 + c) : (c < 40) ? (300 + u0 + c - 20) : (600 + u0 + c - 40);
        w_s[k*60 + c] = rk[(size_t)k*900 + g];
    }
    if (tid < 60) {
        int c = tid;
        int g = (c < 20) ? (u0 + c) : (c < 40) ? (300 + u0 + c - 20) : (600 + u0 + c - 40);
        brec_s[c] = brec[g];
    }
    __syncthreads();

    // GEMM task: warp = kg (k-slice of 20), lane = col-pair (lanes 0..29)
    const int kg = tid >> 5;             // 0..14
    const bool glane = lane < 30;
    const int cp = glane ? lane : 0;     // col pair: cols 2cp, 2cp+1
    const unsigned wbase0 = saddr_of(w_s) + (kg * 20) * 240 + cp * 8;
    const unsigned hbase  = saddr_of(h_s) + (kg * 20) * 80;   // pitch 80B, 16-aligned
    // h staging: this warp stages rows [kg*20, kg*20+20), 8 float2 per row
    const int strow = lane >> 3;         // 0..3 base row (then +4 per j)
    const int stb2  = lane & 7;          // float2 index within row

    // gate task: tid<320 -> (b, u)
    const int gb = tid / 20, gu = tid % 20;
    const int bg = btile + gb;
    const float* xpg = xp + (size_t)bg * T_ * 900 + u0 + gu;

    // prefetch xp + mask for s = 0; h-carry lives in registers
    float xz = 0.f, xr = 0.f, xh = 0.f, hcarry = 0.f;
    unsigned char mpref = 0;
    if (tid < 320) {
        const int t0 = d ? (T_ - 1) : 0;
        const float* p = xpg + (size_t)t0 * 900;
        xz = __ldcg(p); xr = __ldcg(p + 300); xh = __ldcg(p + 600);
        mpref = g_mask8[bg][t0];
    }

    for (int s = 0; s < T_; s++) {
        const int t = d ? (T_ - 1 - s) : s;
        const int cur = s & 1, nxt = cur ^ 1;

        // per-warp wait on the group counter (s=0: passes immediately)
        if (s > 0) {
            if (lane == 0) {
                const int target = 15 * s;
                int v, spins = 0;
                for (;;) {
                    asm volatile("ld.acquire.gpu.global.s32 %0, [%1];"
                                 : "=r"(v) : "l"(bar) : "memory");
                    if (v >= target) break;
                    if (++spins > 64) __nanosleep(64);
                }
            }
            __syncwarp();
        }

        // stage own k-slice of h into smem (warp-private; __syncwarp only)
#pragma unroll
        for (int j = 0; j < 5; j++) {
            int row = strow + j * 4;                       // 0..19
            float2 v = __ldcg((const float2*)&g_h_t[cur][d][kg*20 + row][btile] + stb2);
            *(float2*)&h_s[(kg*20 + row) * 20 + 2*stb2] = v;
        }
        __syncwarp();

        // GEMM: 2 cols x 16 batches over 20 k
        {
            ull a0[8], a1[8];
#pragma unroll
            for (int i = 0; i < 8; i++) { a0[i] = 0ull; a1[i] = 0ull; }
            unsigned wa = wbase0, ha = hbase;
#pragma unroll
            for (int k = 0; k < 20; k++) {
                float w0f, w1f;
                lds_v2f32(w0f, w1f, wa);
                ull h0, h1, h2, h3, h4, h5, h6, h7;
                lds_v2u64(h0, h1, ha);
                lds_v2u64(h2, h3, ha + 16);
                lds_v2u64(h4, h5, ha + 32);
                lds_v2u64(h6, h7, ha + 48);
                ull w0 = bcast2(w0f), w1 = bcast2(w1f);
                fma2(a0[0],h0,w0); fma2(a0[1],h1,w0); fma2(a0[2],h2,w0); fma2(a0[3],h3,w0);
                fma2(a0[4],h4,w0); fma2(a0[5],h5,w0); fma2(a0[6],h6,w0); fma2(a0[7],h7,w0);
                fma2(a1[0],h0,w1); fma2(a1[1],h1,w1); fma2(a1[2],h2,w1); fma2(a1[3],h3,w1);
                fma2(a1[4],h4,w1); fma2(a1[5],h5,w1); fma2(a1[6],h6,w1); fma2(a1[7],h7,w1);
                wa += 240; ha += 80;
            }
            if (glane) {
                ull* rp0 = (ull*)(rp_s + (kg*60 + 2*cp    ) * 16);
                ull* rp1 = (ull*)(rp_s + (kg*60 + 2*cp + 1) * 16);
#pragma unroll
                for (int i = 0; i < 8; i++) { rp0[i] = a0[i]; rp1[i] = a1[i]; }
            }
        }
        __syncthreads();

        // gates: reduce 15 k-slice partials, update state, store h FIRST
        if (tid < 320) {
            float rz = brec_s[gu], rg = brec_s[20+gu], rh = brec_s[40+gu];
#pragma unroll
            for (int q = 0; q < 15; q++) {
                const float* rp = rp_s + q * 960;          // q*60*16
                rz += rp[(gu     )*16 + gb];
                rg += rp[(20 + gu)*16 + gb];
                rh += rp[(40 + gu)*16 + gb];
            }
            float ho = hcarry;
            float z  = sigmoidf_(xz + rz);
            float r  = sigmoidf_(xr + rg);
            float hh = tanh_fast(xh + r * rh);
            float hn = z * ho + (1.f - z) * hh;
            float hc = mpref ? hn : ho;
            float y  = mpref ? hn : 0.f;
            hcarry = hc;
            __stcg(&g_h_t[nxt][d][u0 + gu][bg], hc);
            xz = y;   // stash y; xz is reloaded in the tail prefetch
        }

        // publish: h stores drained block-wide, then release-reduce arrive
        __syncthreads();
        if (tid == 0) {
            asm volatile("red.release.gpu.global.add.s32 [%0], %1;"
                         :: "l"(bar), "r"(1) : "memory");
        }

        // off-critical-path tail: y store + prefetch next xp/mask
        if (tid < 320) {
            out[((size_t)bg * T_ + t) * 600 + d * 300 + u0 + gu] = xz;
            if (s + 1 < T_) {
                const int tn = d ? (T_ - 2 - s) : (s + 1);
                const float* p = xpg + (size_t)tn * 900;
                xz = __ldcg(p); xr = __ldcg(p + 300); xh = __ldcg(p + 600);
                mpref = g_mask8[bg][tn];
            }
        }
    }
}

// ===========================================================
// state = relu(concat(h_f, h_b) @ w_fc + b_fc), grid (64 b, 5 u-tiles)
// ===========================================================
__global__ void __launch_bounds__(256)
k_fc(const float* __restrict__ wfc, const float* __restrict__ bfc,
     float* __restrict__ out) {
    __shared__ float hc[600];
    __shared__ float part[4][64];
    const int b = blockIdx.x, u0 = blockIdx.y * 60, tid = threadIdx.x;
    for (int i = tid; i < 300; i += 256) {
        hc[i]       = g_h_t[0][0][i][b];   // final h lives in buffer 0 (T=1024 even)
        hc[300 + i] = g_h_t[0][1][i][b];
    }
    __syncthreads();
    if (tid < 240) {
        int ut = tid % 60, kg = tid / 60;
        int u = u0 + ut;
        float acc = 0.f;
        const float* wp = wfc + (size_t)(kg*150) * 300 + u;
#pragma unroll 10
        for (int k = 0; k < 150; k++) acc = fmaf(hc[kg*150 + k], wp[(size_t)k*300], acc);
        part[kg][ut] = acc;
    }
    __syncthreads();
    if (tid < 60) {
        float v = part[0][tid] + part[1][tid] + part[2][tid] + part[3][tid] + bfc[u0 + tid];
        out[(size_t)B_ * T_ * 600 + (size_t)b * 300 + u0 + tid] = fmaxf(v, 0.f);
    }
}

// ===========================================================
extern "C" void kernel_launch(void* const* d_in, const int* in_sizes, int n_in,
                              void* d_out, int out_size) {
    const float* x    = (const float*)d_in[0];
    const void*  mask = d_in[1];
    const float* kf   = (const float*)d_in[2];
    const float* rkf  = (const float*)d_in[3];
    const float* bf   = (const float*)d_in[4];
    const float* kb   = (const float*)d_in[5];
    const float* rkb  = (const float*)d_in[6];
    const float* bb   = (const float*)d_in[7];
    const float* wfc  = (const float*)d_in[8];
    const float* bfc  = (const float*)d_in[9];
    float* out = (float*)d_out;

    cudaFuncSetAttribute(k_rnn, cudaFuncAttributeMaxDynamicSharedMemorySize, SMEM_BYTES);

    k_init<<<32, 256>>>(mask);
    k_xp<<<dim3(1024, 15, 2), 256>>>(x, kf, kb, bf, bb);
    k_nop<<<1, 32>>>();   // keeps ncu capture window on k_rnn
    k_rnn<<<NBLK, RNN_THREADS, SMEM_BYTES>>>(rkf, rkb, bf, bb, out);
    k_fc<<<dim3(B_, 5), 256>>>(wfc, bfc, out);
}